// round 8
// baseline (speedup 1.0000x reference)
#include <cuda_runtime.h>
#include <cuda_fp16.h>

#define N_NODES 50000
#define N_EDGES 800000
#define E_TOT   850000
#define F0      128
#define F1      128
#define H1      4
#define C1      32
#define F2      64
#define NEG     0.2f
#define EPS_Z   1e-16f

#define SCAN_B  1024
#define SCAN_G  ((N_NODES + SCAN_B - 1) / SCAN_B)   // 49
#define HALF_N  (N_NODES / 2)                        // 25000

typedef unsigned long long ull;

// ---------------- scratch ----------------
__device__ __half g_h1h[N_NODES * F1];
__device__ float  g_as1[N_NODES * H1];
__device__ float  g_ad1[N_NODES * H1];
__device__ float  g_agg1[N_NODES * F1];
__device__ __half g_h2h[N_NODES * F2];
__device__ float  g_as2[N_NODES];
__device__ float  g_ad2[N_NODES];
__device__ int    g_deg[N_NODES];
__device__ int    g_cur[N_NODES];
__device__ int    g_off[N_NODES + 1];
__device__ int    g_bsum[SCAN_G];
__device__ int    g_bpre[SCAN_G];
__device__ int    g_csr_src[E_TOT];

__device__ __forceinline__ float lrelu(float a) { return (a > 0.f) ? a : NEG * a; }

__device__ __forceinline__ void ffma2(ull& d, ull a, ull b) {
    asm("fma.rn.f32x2 %0, %1, %2, %0;" : "+l"(d) : "l"(a), "l"(b));
}
__device__ __forceinline__ void unpack2(ull v, float& x, float& y) {
    asm("mov.b64 {%0,%1}, %2;" : "=f"(x), "=f"(y) : "l"(v));
}

// ---------------- CSR build ----------------
__global__ void zero_cnt_kernel() {
    int i = blockIdx.x * blockDim.x + threadIdx.x;
    if (i < N_NODES) g_deg[i] = 1;        // self loop pre-counted
}

__global__ void hist_kernel(const int* __restrict__ ei) {
    int e = blockIdx.x * blockDim.x + threadIdx.x;
    if (e >= N_EDGES) return;
    atomicAdd(&g_deg[ei[N_EDGES + e]], 1);
}

__global__ __launch_bounds__(SCAN_B) void scan1_kernel() {
    const int t = threadIdx.x, b = blockIdx.x;
    const int lane = t & 31, warp = t >> 5;
    int i = b * SCAN_B + t;
    int v = (i < N_NODES) ? g_deg[i] : 0;
    int s = v;
    #pragma unroll
    for (int off = 1; off < 32; off <<= 1) {
        int u = __shfl_up_sync(0xffffffffu, s, off);
        if (lane >= off) s += u;
    }
    __shared__ int wsum[32];
    if (lane == 31) wsum[warp] = s;
    __syncthreads();
    if (warp == 0) {
        int ws = wsum[lane];
        #pragma unroll
        for (int off = 1; off < 32; off <<= 1) {
            int u = __shfl_up_sync(0xffffffffu, ws, off);
            if (lane >= off) ws += u;
        }
        wsum[lane] = ws;
    }
    __syncthreads();
    int add = (warp > 0) ? wsum[warp - 1] : 0;
    s += add;
    if (i < N_NODES) g_off[i] = s - v;
    if (t == SCAN_B - 1) g_bsum[b] = s;
}

__global__ void scan2_kernel() {
    const int t = threadIdx.x;           // 64 threads
    __shared__ int sh[64];
    int v = (t < SCAN_G) ? g_bsum[t] : 0;
    sh[t] = v;
    __syncthreads();
    #pragma unroll
    for (int off = 1; off < 64; off <<= 1) {
        int u = (t >= off) ? sh[t - off] : 0;
        __syncthreads();
        sh[t] += u;
        __syncthreads();
    }
    if (t < SCAN_G) g_bpre[t] = sh[t] - v;
    if (t == 63) g_off[N_NODES] = sh[63];
}

__global__ __launch_bounds__(SCAN_B) void scan3_kernel() {
    int i = blockIdx.x * SCAN_B + threadIdx.x;
    if (i >= N_NODES) return;
    int o = g_off[i] + g_bpre[blockIdx.x];
    g_off[i] = o;
    g_csr_src[o] = i;     // self loop in first slot
    g_cur[i] = o + 1;
}

__global__ void scatter_kernel(const int* __restrict__ ei) {
    int e = blockIdx.x * blockDim.x + threadIdx.x;
    if (e >= N_EDGES) return;
    int s = ei[e];
    int d = ei[N_EDGES + e];
    int pos = atomicAdd(&g_cur[d], 1);
    g_csr_src[pos] = s;
}

// ---------------- layer1 GEMM (f32x2) + attention dots, fp16 store ----------------
__global__ __launch_bounds__(128) void gemm1_kernel(
    const float* __restrict__ x, const float* __restrict__ W,
    const float* __restrict__ attS, const float* __restrict__ attD)
{
    __shared__ float2 xs2[8][F0];
    const int t = threadIdx.x;
    const int quad = t & 31, slot = t >> 5;
    const int base = blockIdx.x * 8;

    #pragma unroll
    for (int r = 0; r < 8; r++) {
        float v = x[(long)(base + r) * F0 + t];
        xs2[r][t] = make_float2(v, v);
    }
    __syncthreads();

    const int r0 = slot * 2, r1 = slot * 2 + 1;
    ull a00 = 0, a01 = 0, a10 = 0, a11 = 0;
    const float* Wp = W + quad * 4;
    #pragma unroll 4
    for (int k = 0; k < F0; k++) {
        ulonglong2 w = *(const ulonglong2*)(Wp + (long)k * F1);
        ull xa = *(const ull*)&xs2[r0][k];
        ull xb = *(const ull*)&xs2[r1][k];
        ffma2(a00, w.x, xa); ffma2(a01, w.y, xa);
        ffma2(a10, w.x, xb); ffma2(a11, w.y, xb);
    }

    float4 aS = *(const float4*)&attS[quad * 4];
    float4 aD = *(const float4*)&attD[quad * 4];
    const int head = quad >> 3;

    ull pa[2] = {a00, a10}, pb[2] = {a01, a11};
    #pragma unroll
    for (int r = 0; r < 2; r++) {
        int n = base + slot * 2 + r;
        float v0, v1, v2, v3;
        unpack2(pa[r], v0, v1);
        unpack2(pb[r], v2, v3);
        __half2 h01 = __floats2half2_rn(v0, v1);
        __half2 h23 = __floats2half2_rn(v2, v3);
        uint2 pk;
        pk.x = *(unsigned*)&h01;
        pk.y = *(unsigned*)&h23;
        *(uint2*)&g_h1h[(long)n * F1 + quad * 4] = pk;
        float ps = v0 * aS.x + v1 * aS.y + v2 * aS.z + v3 * aS.w;
        float pd = v0 * aD.x + v1 * aD.y + v2 * aD.z + v3 * aD.w;
        #pragma unroll
        for (int off = 4; off > 0; off >>= 1) {
            ps += __shfl_down_sync(0xffffffffu, ps, off, 8);
            pd += __shfl_down_sync(0xffffffffu, pd, off, 8);
        }
        if ((quad & 7) == 0) {
            g_as1[n * H1 + head] = ps;
            g_ad1[n * H1 + head] = pd;
        }
    }
}

// ---------------- layer1 fused aggregate (warp/node, fp16 gather), node range ----------
__global__ __launch_bounds__(256) void agg1_kernel(int nbeg, int nend) {
    int warp = (blockIdx.x * 256 + threadIdx.x) >> 5;
    int lane = threadIdx.x & 31;
    int n = nbeg + warp;
    if (n >= nend) return;
    const int beg = g_off[n], end = g_off[n + 1];
    const int h = lane >> 3;

    const float adh = g_ad1[n * H1 + h];
    float4 acc = make_float4(0.f, 0.f, 0.f, 0.f);
    float z = 0.f;
    for (int p = beg; p < end; p++) {
        int s = g_csr_src[p];
        float a = g_as1[s * H1 + h];
        uint2 v = *(const uint2*)&g_h1h[(long)s * F1 + lane * 4];
        float e = __expf(lrelu(a + adh));
        z += e;
        float2 f01 = __half22float2(*(__half2*)&v.x);
        float2 f23 = __half22float2(*(__half2*)&v.y);
        acc.x = fmaf(e, f01.x, acc.x);
        acc.y = fmaf(e, f01.y, acc.y);
        acc.z = fmaf(e, f23.x, acc.z);
        acc.w = fmaf(e, f23.y, acc.w);
    }
    float inv = 1.f / (z + EPS_Z);
    float4 o;
    o.x = acc.x * inv; o.y = acc.y * inv; o.z = acc.z * inv; o.w = acc.w * inv;
    *(float4*)&g_agg1[(long)n * F1 + lane * 4] = o;
}

// ---------------- layer2 GEMM (f32x2), fp16 store, node range ----------------
__global__ __launch_bounds__(128) void gemm2_kernel(
    int nbeg,
    const float* __restrict__ b1, const float* __restrict__ W,
    const float* __restrict__ attS, const float* __restrict__ attD)
{
    __shared__ float2 xs2[8][F1];
    const int t = threadIdx.x;
    const int quad = t & 15, slot = t >> 4;
    const int base = nbeg + blockIdx.x * 8;

    #pragma unroll
    for (int r = 0; r < 8; r++) {
        float v = fmaxf(g_agg1[(long)(base + r) * F1 + t] + b1[t], 0.f);
        xs2[r][t] = make_float2(v, v);
    }
    __syncthreads();

    const int n = base + slot;
    ull a0 = 0, a1 = 0;
    const float* Wp = W + quad * 4;
    #pragma unroll 4
    for (int k = 0; k < F1; k++) {
        ulonglong2 w = *(const ulonglong2*)(Wp + (long)k * F2);
        ull xv = *(const ull*)&xs2[slot][k];
        ffma2(a0, w.x, xv); ffma2(a1, w.y, xv);
    }

    float4 aS = *(const float4*)&attS[quad * 4];
    float4 aD = *(const float4*)&attD[quad * 4];
    float v0, v1, v2, v3;
    unpack2(a0, v0, v1);
    unpack2(a1, v2, v3);
    __half2 h01 = __floats2half2_rn(v0, v1);
    __half2 h23 = __floats2half2_rn(v2, v3);
    uint2 pk;
    pk.x = *(unsigned*)&h01;
    pk.y = *(unsigned*)&h23;
    *(uint2*)&g_h2h[(long)n * F2 + quad * 4] = pk;
    float ps = v0 * aS.x + v1 * aS.y + v2 * aS.z + v3 * aS.w;
    float pd = v0 * aD.x + v1 * aD.y + v2 * aD.z + v3 * aD.w;
    #pragma unroll
    for (int off = 8; off > 0; off >>= 1) {
        ps += __shfl_down_sync(0xffffffffu, ps, off, 16);
        pd += __shfl_down_sync(0xffffffffu, pd, off, 16);
    }
    if (quad == 0) {
        g_as2[n] = ps;
        g_ad2[n] = pd;
    }
}

// ---------------- layer2 fused aggregate + bias + relu ----------------
__global__ __launch_bounds__(256) void agg2_kernel(float* __restrict__ out,
                                                   const float* __restrict__ b2) {
    int warp = (blockIdx.x * 256 + threadIdx.x) >> 5;
    int lane = threadIdx.x & 31;
    if (warp >= N_NODES) return;
    const int n = warp;
    const int beg = g_off[n], end = g_off[n + 1];

    const float ad = g_ad2[n];
    float2 acc = make_float2(0.f, 0.f);
    float z = 0.f;
    for (int p = beg; p < end; p++) {
        int s = g_csr_src[p];
        float a = g_as2[s];
        unsigned w = *(const unsigned*)&g_h2h[(long)s * F2 + lane * 2];
        float e = __expf(lrelu(a + ad));
        z += e;
        float2 f = __half22float2(*(__half2*)&w);
        acc.x = fmaf(e, f.x, acc.x);
        acc.y = fmaf(e, f.y, acc.y);
    }
    float inv = 1.f / (z + EPS_Z);
    float2 bb = *(const float2*)&b2[lane * 2];
    float2 o;
    o.x = fmaxf(acc.x * inv + bb.x, 0.f);
    o.y = fmaxf(acc.y * inv + bb.y, 0.f);
    *(float2*)&out[(long)n * F2 + lane * 2] = o;
}

// ---------------- host ----------------
extern "C" void kernel_launch(void* const* d_in, const int* in_sizes, int n_in,
                              void* d_out, int out_size)
{
    const float* x     = (const float*)d_in[0];
    const int*   ei    = (const int*)  d_in[1];
    const float* W1    = (const float*)d_in[2];
    const float* attS1 = (const float*)d_in[3];
    const float* attD1 = (const float*)d_in[4];
    const float* b1    = (const float*)d_in[5];
    const float* W2    = (const float*)d_in[6];
    const float* attS2 = (const float*)d_in[7];
    const float* attD2 = (const float*)d_in[8];
    const float* b2    = (const float*)d_in[9];
    float* out = (float*)d_out;

    static cudaStream_t s2 = nullptr;
    static cudaEvent_t evFork = nullptr, evJoin = nullptr, evA0 = nullptr,
                       evA1 = nullptr, evG = nullptr;
    if (!s2) {
        cudaStreamCreateWithFlags(&s2, cudaStreamNonBlocking);
        cudaEventCreateWithFlags(&evFork, cudaEventDisableTiming);
        cudaEventCreateWithFlags(&evJoin, cudaEventDisableTiming);
        cudaEventCreateWithFlags(&evA0, cudaEventDisableTiming);
        cudaEventCreateWithFlags(&evA1, cudaEventDisableTiming);
        cudaEventCreateWithFlags(&evG, cudaEventDisableTiming);
    }

    const int TB = 256;

    cudaEventRecord(evFork, 0);
    cudaStreamWaitEvent(s2, evFork, 0);

    // launches 0..2: CSR front (main stream)
    zero_cnt_kernel<<<(N_NODES + TB - 1) / TB, TB>>>();
    hist_kernel<<<(N_EDGES + TB - 1) / TB, TB>>>(ei);
    scan1_kernel<<<SCAN_G, SCAN_B>>>();

    // launch 3: gemm1 on s2 (profiled by ncu -s 5 -c 1 index) overlapping CSR build
    gemm1_kernel<<<N_NODES / 8, 128, 0, s2>>>(x, W1, attS1, attD1);
    cudaEventRecord(evJoin, s2);

    // remaining CSR (main stream)
    scan2_kernel<<<1, 64>>>();
    scan3_kernel<<<SCAN_G, SCAN_B>>>();
    scatter_kernel<<<(N_EDGES + TB - 1) / TB, TB>>>(ei);

    // pipelined agg1 / gemm2 halves
    cudaStreamWaitEvent(0, evJoin, 0);
    agg1_kernel<<<(HALF_N * 32 + TB - 1) / TB, TB>>>(0, HALF_N);
    cudaEventRecord(evA0, 0);
    agg1_kernel<<<(HALF_N * 32 + TB - 1) / TB, TB>>>(HALF_N, N_NODES);
    cudaEventRecord(evA1, 0);

    cudaStreamWaitEvent(s2, evA0, 0);
    gemm2_kernel<<<HALF_N / 8, 128, 0, s2>>>(0, b1, W2, attS2, attD2);
    cudaStreamWaitEvent(s2, evA1, 0);
    gemm2_kernel<<<HALF_N / 8, 128, 0, s2>>>(HALF_N, b1, W2, attS2, attD2);
    cudaEventRecord(evG, s2);

    cudaStreamWaitEvent(0, evG, 0);
    agg2_kernel<<<(N_NODES * 32 + TB - 1) / TB, TB>>>(out, b2);
}

// round 10
// speedup vs baseline: 1.1892x; 1.1892x over previous
#include <cuda_runtime.h>
#include <cuda_fp16.h>

#define N_NODES 50000
#define N_EDGES 800000
#define E_TOT   850000
#define F0      128
#define F1      128
#define H1      4
#define C1      32
#define F2      64
#define NEG     0.2f
#define EPS_Z   1e-16f

#define SCAN_B  1024
#define SCAN_G  ((N_NODES + SCAN_B - 1) / SCAN_B)   // 49

typedef unsigned long long ull;

// ---------------- scratch ----------------
__device__ __half g_h1h[N_NODES * F1];
__device__ float  g_as1[N_NODES * H1];
__device__ float  g_ad1[N_NODES * H1];
__device__ float  g_agg1[N_NODES * F1];
__device__ __half g_h2h[N_NODES * F2];
__device__ float  g_as2[N_NODES];
__device__ float  g_ad2[N_NODES];
__device__ int    g_deg[N_NODES];
__device__ int    g_cur[N_NODES];
__device__ int    g_off[N_NODES + 1];
__device__ int    g_bsum[SCAN_G];
__device__ int    g_bpre[SCAN_G];
__device__ int    g_csr_src[E_TOT];

__device__ __forceinline__ float lrelu(float a) { return (a > 0.f) ? a : NEG * a; }

__device__ __forceinline__ void ffma2(ull& d, ull a, ull b) {
    asm("fma.rn.f32x2 %0, %1, %2, %0;" : "+l"(d) : "l"(a), "l"(b));
}
__device__ __forceinline__ void unpack2(ull v, float& x, float& y) {
    asm("mov.b64 {%0,%1}, %2;" : "=f"(x), "=f"(y) : "l"(v));
}

// ---------------- CSR build ----------------
__global__ void zero_cnt_kernel() {
    int i = blockIdx.x * blockDim.x + threadIdx.x;
    if (i < N_NODES) g_deg[i] = 1;        // self loop pre-counted
}

__global__ void hist_kernel(const int* __restrict__ ei) {
    int e = blockIdx.x * blockDim.x + threadIdx.x;
    if (e >= N_EDGES) return;
    atomicAdd(&g_deg[ei[N_EDGES + e]], 1);
}

__global__ __launch_bounds__(SCAN_B) void scan1_kernel() {
    const int t = threadIdx.x, b = blockIdx.x;
    const int lane = t & 31, warp = t >> 5;
    int i = b * SCAN_B + t;
    int v = (i < N_NODES) ? g_deg[i] : 0;
    int s = v;
    #pragma unroll
    for (int off = 1; off < 32; off <<= 1) {
        int u = __shfl_up_sync(0xffffffffu, s, off);
        if (lane >= off) s += u;
    }
    __shared__ int wsum[32];
    if (lane == 31) wsum[warp] = s;
    __syncthreads();
    if (warp == 0) {
        int ws = wsum[lane];
        #pragma unroll
        for (int off = 1; off < 32; off <<= 1) {
            int u = __shfl_up_sync(0xffffffffu, ws, off);
            if (lane >= off) ws += u;
        }
        wsum[lane] = ws;
    }
    __syncthreads();
    int add = (warp > 0) ? wsum[warp - 1] : 0;
    s += add;
    if (i < N_NODES) g_off[i] = s - v;
    if (t == SCAN_B - 1) g_bsum[b] = s;
}

__global__ void scan2_kernel() {
    const int t = threadIdx.x;           // 64 threads
    __shared__ int sh[64];
    int v = (t < SCAN_G) ? g_bsum[t] : 0;
    sh[t] = v;
    __syncthreads();
    #pragma unroll
    for (int off = 1; off < 64; off <<= 1) {
        int u = (t >= off) ? sh[t - off] : 0;
        __syncthreads();
        sh[t] += u;
        __syncthreads();
    }
    if (t < SCAN_G) g_bpre[t] = sh[t] - v;
    if (t == 63) g_off[N_NODES] = sh[63];
}

__global__ __launch_bounds__(SCAN_B) void scan3_kernel() {
    int i = blockIdx.x * SCAN_B + threadIdx.x;
    if (i >= N_NODES) return;
    int o = g_off[i] + g_bpre[blockIdx.x];
    g_off[i] = o;
    g_csr_src[o] = i;     // self loop in first slot
    g_cur[i] = o + 1;
}

__global__ void scatter_kernel(const int* __restrict__ ei) {
    int e = blockIdx.x * blockDim.x + threadIdx.x;
    if (e >= N_EDGES) return;
    int s = ei[e];
    int d = ei[N_EDGES + e];
    int pos = atomicAdd(&g_cur[d], 1);
    g_csr_src[pos] = s;
}

// ---------------- layer1 GEMM: 16 nodes/block, 4 nodes/thread ----------------
__global__ __launch_bounds__(128) void gemm1_kernel(
    const float* __restrict__ x, const float* __restrict__ W,
    const float* __restrict__ attS, const float* __restrict__ attD)
{
    __shared__ float2 xs2[16][F0];
    const int t = threadIdx.x;
    const int quad = t & 31, slot = t >> 5;
    const int base = blockIdx.x * 16;

    #pragma unroll
    for (int r = 0; r < 16; r++) {
        float v = x[(long)(base + r) * F0 + t];
        xs2[r][t] = make_float2(v, v);
    }
    __syncthreads();

    const int n0 = slot * 4;
    ull acc[4][2] = {};
    const float* Wp = W + quad * 4;
    #pragma unroll 4
    for (int k = 0; k < F0; k++) {
        ulonglong2 w = *(const ulonglong2*)(Wp + (long)k * F1);
        #pragma unroll
        for (int r = 0; r < 4; r++) {
            ull xv = *(const ull*)&xs2[n0 + r][k];
            ffma2(acc[r][0], w.x, xv);
            ffma2(acc[r][1], w.y, xv);
        }
    }

    float4 aS = *(const float4*)&attS[quad * 4];
    float4 aD = *(const float4*)&attD[quad * 4];
    const int head = quad >> 3;

    #pragma unroll
    for (int r = 0; r < 4; r++) {
        int n = base + n0 + r;
        float v0, v1, v2, v3;
        unpack2(acc[r][0], v0, v1);
        unpack2(acc[r][1], v2, v3);
        __half2 h01 = __floats2half2_rn(v0, v1);
        __half2 h23 = __floats2half2_rn(v2, v3);
        uint2 pk;
        pk.x = *(unsigned*)&h01;
        pk.y = *(unsigned*)&h23;
        *(uint2*)&g_h1h[(long)n * F1 + quad * 4] = pk;
        float ps = v0 * aS.x + v1 * aS.y + v2 * aS.z + v3 * aS.w;
        float pd = v0 * aD.x + v1 * aD.y + v2 * aD.z + v3 * aD.w;
        #pragma unroll
        for (int off = 4; off > 0; off >>= 1) {
            ps += __shfl_down_sync(0xffffffffu, ps, off, 8);
            pd += __shfl_down_sync(0xffffffffu, pd, off, 8);
        }
        if ((quad & 7) == 0) {
            g_as1[n * H1 + head] = ps;
            g_ad1[n * H1 + head] = pd;
        }
    }
}

// ---------------- layer1 fused aggregate (warp/node, fp16 gather) ----------------
__global__ __launch_bounds__(256) void agg1_kernel() {
    int warp = (blockIdx.x * 256 + threadIdx.x) >> 5;
    int lane = threadIdx.x & 31;
    if (warp >= N_NODES) return;
    const int n = warp;
    const int beg = g_off[n], end = g_off[n + 1];
    const int h = lane >> 3;

    const float adh = g_ad1[n * H1 + h];
    float4 acc = make_float4(0.f, 0.f, 0.f, 0.f);
    float z = 0.f;
    for (int p = beg; p < end; p++) {
        int s = g_csr_src[p];
        float a = g_as1[s * H1 + h];
        uint2 v = *(const uint2*)&g_h1h[(long)s * F1 + lane * 4];
        float e = __expf(lrelu(a + adh));
        z += e;
        float2 f01 = __half22float2(*(__half2*)&v.x);
        float2 f23 = __half22float2(*(__half2*)&v.y);
        acc.x = fmaf(e, f01.x, acc.x);
        acc.y = fmaf(e, f01.y, acc.y);
        acc.z = fmaf(e, f23.x, acc.z);
        acc.w = fmaf(e, f23.y, acc.w);
    }
    float inv = 1.f / (z + EPS_Z);
    float4 o;
    o.x = acc.x * inv; o.y = acc.y * inv; o.z = acc.z * inv; o.w = acc.w * inv;
    *(float4*)&g_agg1[(long)n * F1 + lane * 4] = o;
}

// ---------------- layer2 GEMM: 16 nodes/block, 2 nodes/thread ----------------
__global__ __launch_bounds__(128) void gemm2_kernel(
    const float* __restrict__ b1, const float* __restrict__ W,
    const float* __restrict__ attS, const float* __restrict__ attD)
{
    __shared__ float2 xs2[16][F1];
    const int t = threadIdx.x;
    const int quad = t & 15, slot = t >> 4;
    const int base = blockIdx.x * 16;

    #pragma unroll
    for (int r = 0; r < 16; r++) {
        float v = fmaxf(g_agg1[(long)(base + r) * F1 + t] + b1[t], 0.f);
        xs2[r][t] = make_float2(v, v);
    }
    __syncthreads();

    const int r0 = slot * 2, r1 = slot * 2 + 1;
    ull a00 = 0, a01 = 0, a10 = 0, a11 = 0;
    const float* Wp = W + quad * 4;
    #pragma unroll 4
    for (int k = 0; k < F1; k++) {
        ulonglong2 w = *(const ulonglong2*)(Wp + (long)k * F2);
        ull xa = *(const ull*)&xs2[r0][k];
        ull xb = *(const ull*)&xs2[r1][k];
        ffma2(a00, w.x, xa); ffma2(a01, w.y, xa);
        ffma2(a10, w.x, xb); ffma2(a11, w.y, xb);
    }

    float4 aS = *(const float4*)&attS[quad * 4];
    float4 aD = *(const float4*)&attD[quad * 4];

    ull pa[2] = {a00, a10}, pb[2] = {a01, a11};
    #pragma unroll
    for (int r = 0; r < 2; r++) {
        int n = base + slot * 2 + r;
        float v0, v1, v2, v3;
        unpack2(pa[r], v0, v1);
        unpack2(pb[r], v2, v3);
        __half2 h01 = __floats2half2_rn(v0, v1);
        __half2 h23 = __floats2half2_rn(v2, v3);
        uint2 pk;
        pk.x = *(unsigned*)&h01;
        pk.y = *(unsigned*)&h23;
        *(uint2*)&g_h2h[(long)n * F2 + quad * 4] = pk;
        float ps = v0 * aS.x + v1 * aS.y + v2 * aS.z + v3 * aS.w;
        float pd = v0 * aD.x + v1 * aD.y + v2 * aD.z + v3 * aD.w;
        #pragma unroll
        for (int off = 8; off > 0; off >>= 1) {
            ps += __shfl_down_sync(0xffffffffu, ps, off, 16);
            pd += __shfl_down_sync(0xffffffffu, pd, off, 16);
        }
        if (quad == 0) {
            g_as2[n] = ps;
            g_ad2[n] = pd;
        }
    }
}

// ---------------- layer2 fused aggregate + bias + relu ----------------
__global__ __launch_bounds__(256) void agg2_kernel(float* __restrict__ out,
                                                   const float* __restrict__ b2) {
    int warp = (blockIdx.x * 256 + threadIdx.x) >> 5;
    int lane = threadIdx.x & 31;
    if (warp >= N_NODES) return;
    const int n = warp;
    const int beg = g_off[n], end = g_off[n + 1];

    const float ad = g_ad2[n];
    float2 acc = make_float2(0.f, 0.f);
    float z = 0.f;
    for (int p = beg; p < end; p++) {
        int s = g_csr_src[p];
        float a = g_as2[s];
        unsigned w = *(const unsigned*)&g_h2h[(long)s * F2 + lane * 2];
        float e = __expf(lrelu(a + ad));
        z += e;
        float2 f = __half22float2(*(__half2*)&w);
        acc.x = fmaf(e, f.x, acc.x);
        acc.y = fmaf(e, f.y, acc.y);
    }
    float inv = 1.f / (z + EPS_Z);
    float2 bb = *(const float2*)&b2[lane * 2];
    float2 o;
    o.x = fmaxf(acc.x * inv + bb.x, 0.f);
    o.y = fmaxf(acc.y * inv + bb.y, 0.f);
    *(float2*)&out[(long)n * F2 + lane * 2] = o;
}

// ---------------- host ----------------
extern "C" void kernel_launch(void* const* d_in, const int* in_sizes, int n_in,
                              void* d_out, int out_size)
{
    const float* x     = (const float*)d_in[0];
    const int*   ei    = (const int*)  d_in[1];
    const float* W1    = (const float*)d_in[2];
    const float* attS1 = (const float*)d_in[3];
    const float* attD1 = (const float*)d_in[4];
    const float* b1    = (const float*)d_in[5];
    const float* W2    = (const float*)d_in[6];
    const float* attS2 = (const float*)d_in[7];
    const float* attD2 = (const float*)d_in[8];
    const float* b2    = (const float*)d_in[9];
    float* out = (float*)d_out;

    static cudaStream_t s2 = nullptr;
    static cudaEvent_t evFork = nullptr, evJoin = nullptr;
    if (!s2) {
        cudaStreamCreateWithFlags(&s2, cudaStreamNonBlocking);
        cudaEventCreateWithFlags(&evFork, cudaEventDisableTiming);
        cudaEventCreateWithFlags(&evJoin, cudaEventDisableTiming);
    }

    const int TB = 256;

    cudaEventRecord(evFork, 0);
    cudaStreamWaitEvent(s2, evFork, 0);

    // launches 0..2: CSR front (main stream)
    zero_cnt_kernel<<<(N_NODES + TB - 1) / TB, TB>>>();
    hist_kernel<<<(N_EDGES + TB - 1) / TB, TB>>>(ei);
    scan1_kernel<<<SCAN_G, SCAN_B>>>();

    // launch 3: gemm1 on s2 (ncu profiles launch idx 3) overlapping CSR build
    gemm1_kernel<<<N_NODES / 16, 128, 0, s2>>>(x, W1, attS1, attD1);
    cudaEventRecord(evJoin, s2);

    // remaining CSR (main stream)
    scan2_kernel<<<1, 64>>>();
    scan3_kernel<<<SCAN_G, SCAN_B>>>();
    scatter_kernel<<<(N_EDGES + TB - 1) / TB, TB>>>(ei);

    // join, then layer-1 aggregate + layer 2 (main stream, full width)
    cudaStreamWaitEvent(0, evJoin, 0);
    agg1_kernel<<<(N_NODES * 32 + TB - 1) / TB, TB>>>();
    gemm2_kernel<<<N_NODES / 16, 128>>>(b1, W2, attS2, attD2);
    agg2_kernel<<<(N_NODES * 32 + TB - 1) / TB, TB>>>(out, b2);
}

// round 11
// speedup vs baseline: 1.2398x; 1.0425x over previous
#include <cuda_runtime.h>
#include <cuda_fp16.h>

#define N_NODES 50000
#define N_EDGES 800000
#define E_TOT   850000
#define F0      128
#define F1      128
#define H1      4
#define C1      32
#define F2      64
#define NEG     0.2f
#define EPS_Z   1e-16f

#define SCAN_B  1024
#define SCAN_G  ((N_NODES + SCAN_B - 1) / SCAN_B)   // 49
#define G1_NODES 32
#define G1_GRID  ((N_NODES + G1_NODES - 1) / G1_NODES)  // 1563

typedef unsigned long long ull;

// ---------------- scratch ----------------
__device__ __half g_h1h[N_NODES * F1];
__device__ float  g_as1[N_NODES * H1];
__device__ float  g_ad1[N_NODES * H1];
__device__ float  g_agg1[N_NODES * F1];
__device__ __half g_h2h[N_NODES * F2];
__device__ float  g_as2[N_NODES];
__device__ float  g_ad2[N_NODES];
__device__ int    g_deg[N_NODES];
__device__ int    g_cur[N_NODES];
__device__ int    g_off[N_NODES + 1];
__device__ int    g_bsum[SCAN_G];
__device__ int    g_bpre[SCAN_G];
__device__ int    g_csr_src[E_TOT];

__device__ __forceinline__ float lrelu(float a) { return (a > 0.f) ? a : NEG * a; }

__device__ __forceinline__ void ffma2(ull& d, ull a, ull b) {
    asm("fma.rn.f32x2 %0, %1, %2, %0;" : "+l"(d) : "l"(a), "l"(b));
}
__device__ __forceinline__ void unpack2(ull v, float& x, float& y) {
    asm("mov.b64 {%0,%1}, %2;" : "=f"(x), "=f"(y) : "l"(v));
}

// ---------------- CSR build ----------------
__global__ void zero_cnt_kernel() {
    int i = blockIdx.x * blockDim.x + threadIdx.x;
    if (i < N_NODES) g_deg[i] = 1;        // self loop pre-counted
}

__global__ void hist_kernel(const int* __restrict__ ei) {
    int e = blockIdx.x * blockDim.x + threadIdx.x;
    if (e >= N_EDGES) return;
    atomicAdd(&g_deg[ei[N_EDGES + e]], 1);
}

__global__ __launch_bounds__(SCAN_B) void scan1_kernel() {
    const int t = threadIdx.x, b = blockIdx.x;
    const int lane = t & 31, warp = t >> 5;
    int i = b * SCAN_B + t;
    int v = (i < N_NODES) ? g_deg[i] : 0;
    int s = v;
    #pragma unroll
    for (int off = 1; off < 32; off <<= 1) {
        int u = __shfl_up_sync(0xffffffffu, s, off);
        if (lane >= off) s += u;
    }
    __shared__ int wsum[32];
    if (lane == 31) wsum[warp] = s;
    __syncthreads();
    if (warp == 0) {
        int ws = wsum[lane];
        #pragma unroll
        for (int off = 1; off < 32; off <<= 1) {
            int u = __shfl_up_sync(0xffffffffu, ws, off);
            if (lane >= off) ws += u;
        }
        wsum[lane] = ws;
    }
    __syncthreads();
    int add = (warp > 0) ? wsum[warp - 1] : 0;
    s += add;
    if (i < N_NODES) g_off[i] = s - v;
    if (t == SCAN_B - 1) g_bsum[b] = s;
}

__global__ void scan2_kernel() {
    const int t = threadIdx.x;           // 64 threads
    __shared__ int sh[64];
    int v = (t < SCAN_G) ? g_bsum[t] : 0;
    sh[t] = v;
    __syncthreads();
    #pragma unroll
    for (int off = 1; off < 64; off <<= 1) {
        int u = (t >= off) ? sh[t - off] : 0;
        __syncthreads();
        sh[t] += u;
        __syncthreads();
    }
    if (t < SCAN_G) g_bpre[t] = sh[t] - v;
    if (t == 63) g_off[N_NODES] = sh[63];
}

__global__ __launch_bounds__(SCAN_B) void scan3_kernel() {
    int i = blockIdx.x * SCAN_B + threadIdx.x;
    if (i >= N_NODES) return;
    int o = g_off[i] + g_bpre[blockIdx.x];
    g_off[i] = o;
    g_csr_src[o] = i;     // self loop in first slot
    g_cur[i] = o + 1;
}

__global__ void scatter_kernel(const int* __restrict__ ei) {
    int e = blockIdx.x * blockDim.x + threadIdx.x;
    if (e >= N_EDGES) return;
    int s = ei[e];
    int d = ei[N_EDGES + e];
    int pos = atomicAdd(&g_cur[d], 1);
    g_csr_src[pos] = s;
}

// ---------------- layer1 GEMM: 32 nodes/block, 8 nodes/thread ----------------
// lane/quad = t&31 (channels quad*4..+3), slot = t>>5 (nodes slot*8..slot*8+7)
__global__ __launch_bounds__(128) void gemm1_kernel(
    const float* __restrict__ x, const float* __restrict__ W,
    const float* __restrict__ attS, const float* __restrict__ attD)
{
    __shared__ float2 xs2[G1_NODES][F0];
    const int t = threadIdx.x;
    const int quad = t & 31, slot = t >> 5;
    const int base = blockIdx.x * G1_NODES;

    #pragma unroll
    for (int r = 0; r < G1_NODES; r++) {
        int n = base + r;
        float v = (n < N_NODES) ? x[(long)n * F0 + t] : 0.f;
        xs2[r][t] = make_float2(v, v);
    }
    __syncthreads();

    const int n0 = slot * 8;
    ull acc[8][2] = {};
    const float* Wp = W + quad * 4;
    #pragma unroll 2
    for (int k = 0; k < F0; k++) {
        ulonglong2 w = *(const ulonglong2*)(Wp + (long)k * F1);
        #pragma unroll
        for (int r = 0; r < 8; r++) {
            ull xv = *(const ull*)&xs2[n0 + r][k];
            ffma2(acc[r][0], w.x, xv);
            ffma2(acc[r][1], w.y, xv);
        }
    }

    float4 aS = *(const float4*)&attS[quad * 4];
    float4 aD = *(const float4*)&attD[quad * 4];
    const int head = quad >> 3;

    #pragma unroll
    for (int r = 0; r < 8; r++) {
        int n = base + n0 + r;
        float v0, v1, v2, v3;
        unpack2(acc[r][0], v0, v1);
        unpack2(acc[r][1], v2, v3);
        float ps = v0 * aS.x + v1 * aS.y + v2 * aS.z + v3 * aS.w;
        float pd = v0 * aD.x + v1 * aD.y + v2 * aD.z + v3 * aD.w;
        #pragma unroll
        for (int off = 4; off > 0; off >>= 1) {
            ps += __shfl_down_sync(0xffffffffu, ps, off, 8);
            pd += __shfl_down_sync(0xffffffffu, pd, off, 8);
        }
        if (n < N_NODES) {
            __half2 h01 = __floats2half2_rn(v0, v1);
            __half2 h23 = __floats2half2_rn(v2, v3);
            uint2 pk;
            pk.x = *(unsigned*)&h01;
            pk.y = *(unsigned*)&h23;
            *(uint2*)&g_h1h[(long)n * F1 + quad * 4] = pk;
            if ((quad & 7) == 0) {
                g_as1[n * H1 + head] = ps;
                g_ad1[n * H1 + head] = pd;
            }
        }
    }
}

// ---------------- layer1 fused aggregate (warp/node, fp16 gather) ----------------
__global__ __launch_bounds__(256) void agg1_kernel() {
    int warp = (blockIdx.x * 256 + threadIdx.x) >> 5;
    int lane = threadIdx.x & 31;
    if (warp >= N_NODES) return;
    const int n = warp;
    const int beg = g_off[n], end = g_off[n + 1];
    const int h = lane >> 3;

    const float adh = g_ad1[n * H1 + h];
    float4 acc = make_float4(0.f, 0.f, 0.f, 0.f);
    float z = 0.f;
    for (int p = beg; p < end; p++) {
        int s = g_csr_src[p];
        float a = g_as1[s * H1 + h];
        uint2 v = *(const uint2*)&g_h1h[(long)s * F1 + lane * 4];
        float e = __expf(lrelu(a + adh));
        z += e;
        float2 f01 = __half22float2(*(__half2*)&v.x);
        float2 f23 = __half22float2(*(__half2*)&v.y);
        acc.x = fmaf(e, f01.x, acc.x);
        acc.y = fmaf(e, f01.y, acc.y);
        acc.z = fmaf(e, f23.x, acc.z);
        acc.w = fmaf(e, f23.y, acc.w);
    }
    float inv = 1.f / (z + EPS_Z);
    float4 o;
    o.x = acc.x * inv; o.y = acc.y * inv; o.z = acc.z * inv; o.w = acc.w * inv;
    *(float4*)&g_agg1[(long)n * F1 + lane * 4] = o;
}

// ---------------- layer2 GEMM: 16 nodes/block, 2 nodes/thread ----------------
__global__ __launch_bounds__(128) void gemm2_kernel(
    const float* __restrict__ b1, const float* __restrict__ W,
    const float* __restrict__ attS, const float* __restrict__ attD)
{
    __shared__ float2 xs2[16][F1];
    const int t = threadIdx.x;
    const int quad = t & 15, slot = t >> 4;
    const int base = blockIdx.x * 16;

    #pragma unroll
    for (int r = 0; r < 16; r++) {
        float v = fmaxf(g_agg1[(long)(base + r) * F1 + t] + b1[t], 0.f);
        xs2[r][t] = make_float2(v, v);
    }
    __syncthreads();

    const int r0 = slot * 2, r1 = slot * 2 + 1;
    ull a00 = 0, a01 = 0, a10 = 0, a11 = 0;
    const float* Wp = W + quad * 4;
    #pragma unroll 4
    for (int k = 0; k < F1; k++) {
        ulonglong2 w = *(const ulonglong2*)(Wp + (long)k * F2);
        ull xa = *(const ull*)&xs2[r0][k];
        ull xb = *(const ull*)&xs2[r1][k];
        ffma2(a00, w.x, xa); ffma2(a01, w.y, xa);
        ffma2(a10, w.x, xb); ffma2(a11, w.y, xb);
    }

    float4 aS = *(const float4*)&attS[quad * 4];
    float4 aD = *(const float4*)&attD[quad * 4];

    ull pa[2] = {a00, a10}, pb[2] = {a01, a11};
    #pragma unroll
    for (int r = 0; r < 2; r++) {
        int n = base + slot * 2 + r;
        float v0, v1, v2, v3;
        unpack2(pa[r], v0, v1);
        unpack2(pb[r], v2, v3);
        __half2 h01 = __floats2half2_rn(v0, v1);
        __half2 h23 = __floats2half2_rn(v2, v3);
        uint2 pk;
        pk.x = *(unsigned*)&h01;
        pk.y = *(unsigned*)&h23;
        *(uint2*)&g_h2h[(long)n * F2 + quad * 4] = pk;
        float ps = v0 * aS.x + v1 * aS.y + v2 * aS.z + v3 * aS.w;
        float pd = v0 * aD.x + v1 * aD.y + v2 * aD.z + v3 * aD.w;
        #pragma unroll
        for (int off = 8; off > 0; off >>= 1) {
            ps += __shfl_down_sync(0xffffffffu, ps, off, 16);
            pd += __shfl_down_sync(0xffffffffu, pd, off, 16);
        }
        if (quad == 0) {
            g_as2[n] = ps;
            g_ad2[n] = pd;
        }
    }
}

// ---------------- layer2 fused aggregate + bias + relu ----------------
__global__ __launch_bounds__(256) void agg2_kernel(float* __restrict__ out,
                                                   const float* __restrict__ b2) {
    int warp = (blockIdx.x * 256 + threadIdx.x) >> 5;
    int lane = threadIdx.x & 31;
    if (warp >= N_NODES) return;
    const int n = warp;
    const int beg = g_off[n], end = g_off[n + 1];

    const float ad = g_ad2[n];
    float2 acc = make_float2(0.f, 0.f);
    float z = 0.f;
    for (int p = beg; p < end; p++) {
        int s = g_csr_src[p];
        float a = g_as2[s];
        unsigned w = *(const unsigned*)&g_h2h[(long)s * F2 + lane * 2];
        float e = __expf(lrelu(a + ad));
        z += e;
        float2 f = __half22float2(*(__half2*)&w);
        acc.x = fmaf(e, f.x, acc.x);
        acc.y = fmaf(e, f.y, acc.y);
    }
    float inv = 1.f / (z + EPS_Z);
    float2 bb = *(const float2*)&b2[lane * 2];
    float2 o;
    o.x = fmaxf(acc.x * inv + bb.x, 0.f);
    o.y = fmaxf(acc.y * inv + bb.y, 0.f);
    *(float2*)&out[(long)n * F2 + lane * 2] = o;
}

// ---------------- host ----------------
extern "C" void kernel_launch(void* const* d_in, const int* in_sizes, int n_in,
                              void* d_out, int out_size)
{
    const float* x     = (const float*)d_in[0];
    const int*   ei    = (const int*)  d_in[1];
    const float* W1    = (const float*)d_in[2];
    const float* attS1 = (const float*)d_in[3];
    const float* attD1 = (const float*)d_in[4];
    const float* b1    = (const float*)d_in[5];
    const float* W2    = (const float*)d_in[6];
    const float* attS2 = (const float*)d_in[7];
    const float* attD2 = (const float*)d_in[8];
    const float* b2    = (const float*)d_in[9];
    float* out = (float*)d_out;

    static cudaStream_t s2 = nullptr;
    static cudaEvent_t evFork = nullptr, evJoin = nullptr;
    if (!s2) {
        cudaStreamCreateWithFlags(&s2, cudaStreamNonBlocking);
        cudaEventCreateWithFlags(&evFork, cudaEventDisableTiming);
        cudaEventCreateWithFlags(&evJoin, cudaEventDisableTiming);
    }

    const int TB = 256;

    cudaEventRecord(evFork, 0);
    cudaStreamWaitEvent(s2, evFork, 0);

    // launches 0..2: CSR front (main stream)
    zero_cnt_kernel<<<(N_NODES + TB - 1) / TB, TB>>>();
    hist_kernel<<<(N_EDGES + TB - 1) / TB, TB>>>(ei);
    scan1_kernel<<<SCAN_G, SCAN_B>>>();

    // launch 3: gemm1 on s2 (ncu profiles launch idx 3) overlapping CSR build
    gemm1_kernel<<<G1_GRID, 128, 0, s2>>>(x, W1, attS1, attD1);
    cudaEventRecord(evJoin, s2);

    // remaining CSR (main stream)
    scan2_kernel<<<1, 64>>>();
    scan3_kernel<<<SCAN_G, SCAN_B>>>();
    scatter_kernel<<<(N_EDGES + TB - 1) / TB, TB>>>(ei);

    // join, then layer-1 aggregate + layer 2 (main stream)
    cudaStreamWaitEvent(0, evJoin, 0);
    agg1_kernel<<<(N_NODES * 32 + TB - 1) / TB, TB>>>();
    gemm2_kernel<<<N_NODES / 16, 128>>>(b1, W2, attS2, attD2);
    agg2_kernel<<<(N_NODES * 32 + TB - 1) / TB, TB>>>(out, b2);
}

// round 12
// speedup vs baseline: 1.5212x; 1.2270x over previous
#include <cuda_runtime.h>
#include <cuda_fp16.h>

#define N_NODES 50000
#define N_EDGES 800000
#define E_TOT   850000
#define F0      128
#define F1      128
#define H1      4
#define C1      32
#define F2      64
#define NEG     0.2f
#define EPS_Z   1e-16f

#define SCAN_B  1024
#define SCAN_G  ((N_NODES + SCAN_B - 1) / SCAN_B)   // 49
#define G1_BM   64
#define G1_GRID ((N_NODES + G1_BM - 1) / G1_BM)     // 782

typedef unsigned long long ull;

// ---------------- scratch ----------------
__device__ __half g_h1h[N_NODES * F1];
__device__ float  g_as1[N_NODES * H1];
__device__ float  g_ad1[N_NODES * H1];
__device__ float  g_agg1[N_NODES * F1];
__device__ __half g_h2h[N_NODES * F2];
__device__ float  g_as2[N_NODES];
__device__ float  g_ad2[N_NODES];
__device__ int    g_deg[N_NODES];
__device__ int    g_cur[N_NODES];
__device__ int    g_off[N_NODES + 1];
__device__ int    g_bsum[SCAN_G];
__device__ int    g_bpre[SCAN_G];
__device__ int    g_csr_src[E_TOT];

__device__ __forceinline__ float lrelu(float a) { return (a > 0.f) ? a : NEG * a; }

__device__ __forceinline__ void ffma2(ull& d, ull a, ull b) {
    asm("fma.rn.f32x2 %0, %1, %2, %0;" : "+l"(d) : "l"(a), "l"(b));
}
__device__ __forceinline__ void unpack2(ull v, float& x, float& y) {
    asm("mov.b64 {%0,%1}, %2;" : "=f"(x), "=f"(y) : "l"(v));
}

__device__ __forceinline__ unsigned smaddr(const void* p) {
    return (unsigned)__cvta_generic_to_shared(p);
}
__device__ __forceinline__ void ldm_a4(unsigned& a0, unsigned& a1, unsigned& a2, unsigned& a3,
                                       unsigned addr) {
    asm volatile("ldmatrix.sync.aligned.m8n8.x4.shared.b16 {%0,%1,%2,%3}, [%4];"
                 : "=r"(a0), "=r"(a1), "=r"(a2), "=r"(a3) : "r"(addr));
}
__device__ __forceinline__ void ldm_b2t(unsigned& b0, unsigned& b1, unsigned addr) {
    asm volatile("ldmatrix.sync.aligned.m8n8.x2.trans.shared.b16 {%0,%1}, [%2];"
                 : "=r"(b0), "=r"(b1) : "r"(addr));
}
__device__ __forceinline__ void mma16816(float* d,
                                         unsigned a0, unsigned a1, unsigned a2, unsigned a3,
                                         unsigned b0, unsigned b1) {
    asm volatile("mma.sync.aligned.m16n8k16.row.col.f32.f16.f16.f32 "
                 "{%0,%1,%2,%3}, {%4,%5,%6,%7}, {%8,%9}, {%0,%1,%2,%3};"
                 : "+f"(d[0]), "+f"(d[1]), "+f"(d[2]), "+f"(d[3])
                 : "r"(a0), "r"(a1), "r"(a2), "r"(a3), "r"(b0), "r"(b1));
}

// ---------------- CSR build ----------------
__global__ void zero_cnt_kernel() {
    int i = blockIdx.x * blockDim.x + threadIdx.x;
    if (i < N_NODES) g_deg[i] = 1;        // self loop pre-counted
}

__global__ void hist_kernel(const int* __restrict__ ei) {
    int e = blockIdx.x * blockDim.x + threadIdx.x;
    if (e >= N_EDGES) return;
    atomicAdd(&g_deg[ei[N_EDGES + e]], 1);
}

__global__ __launch_bounds__(SCAN_B) void scan1_kernel() {
    const int t = threadIdx.x, b = blockIdx.x;
    const int lane = t & 31, warp = t >> 5;
    int i = b * SCAN_B + t;
    int v = (i < N_NODES) ? g_deg[i] : 0;
    int s = v;
    #pragma unroll
    for (int off = 1; off < 32; off <<= 1) {
        int u = __shfl_up_sync(0xffffffffu, s, off);
        if (lane >= off) s += u;
    }
    __shared__ int wsum[32];
    if (lane == 31) wsum[warp] = s;
    __syncthreads();
    if (warp == 0) {
        int ws = wsum[lane];
        #pragma unroll
        for (int off = 1; off < 32; off <<= 1) {
            int u = __shfl_up_sync(0xffffffffu, ws, off);
            if (lane >= off) ws += u;
        }
        wsum[lane] = ws;
    }
    __syncthreads();
    int add = (warp > 0) ? wsum[warp - 1] : 0;
    s += add;
    if (i < N_NODES) g_off[i] = s - v;
    if (t == SCAN_B - 1) g_bsum[b] = s;
}

__global__ void scan2_kernel() {
    const int t = threadIdx.x;           // 64 threads
    __shared__ int sh[64];
    int v = (t < SCAN_G) ? g_bsum[t] : 0;
    sh[t] = v;
    __syncthreads();
    #pragma unroll
    for (int off = 1; off < 64; off <<= 1) {
        int u = (t >= off) ? sh[t - off] : 0;
        __syncthreads();
        sh[t] += u;
        __syncthreads();
    }
    if (t < SCAN_G) g_bpre[t] = sh[t] - v;
    if (t == 63) g_off[N_NODES] = sh[63];
}

__global__ __launch_bounds__(SCAN_B) void scan3_kernel() {
    int i = blockIdx.x * SCAN_B + threadIdx.x;
    if (i >= N_NODES) return;
    int o = g_off[i] + g_bpre[blockIdx.x];
    g_off[i] = o;
    g_csr_src[o] = i;     // self loop in first slot
    g_cur[i] = o + 1;
}

__global__ void scatter_kernel(const int* __restrict__ ei) {
    int e = blockIdx.x * blockDim.x + threadIdx.x;
    if (e >= N_EDGES) return;
    int s = ei[e];
    int d = ei[N_EDGES + e];
    int pos = atomicAdd(&g_cur[d], 1);
    g_csr_src[pos] = s;
}

// ---------------- layer1 GEMM via fp16 tensor cores ----------------
// 128 threads = 4 warps; BM=64 (16 rows/warp), BN=128, BK=128.
// Xs: 64x128 fp16 swizzled; Ws: 128x128 fp16 swizzled (16B granule ^ (row&7)).
__global__ __launch_bounds__(128) void gemm1_kernel(
    const float* __restrict__ x, const float* __restrict__ W,
    const float* __restrict__ attS, const float* __restrict__ attD)
{
    __shared__ __align__(16) __half Xs[G1_BM * F0];
    __shared__ __align__(16) __half Ws[F0 * F1];
    const int t = threadIdx.x;
    const int lane = t & 31, w = t >> 5;
    const int base = blockIdx.x * G1_BM;

    // stage X tile (fp32 -> fp16, swizzled)
    #pragma unroll
    for (int i = 0; i < 16; i++) {
        int f = i * 128 + t;              // 0..2047
        int row = f >> 5, q4 = f & 31;    // q4 = float4 index in row
        int n = base + row;
        float4 v = (n < N_NODES) ? *(const float4*)&x[(long)n * F0 + q4 * 4]
                                 : make_float4(0.f, 0.f, 0.f, 0.f);
        __half2 p0 = __floats2half2_rn(v.x, v.y);
        __half2 p1 = __floats2half2_rn(v.z, v.w);
        uint2 st;
        st.x = *(unsigned*)&p0;
        st.y = *(unsigned*)&p1;
        int phys = (q4 >> 1) ^ (row & 7);
        *(uint2*)((char*)Xs + row * 256 + phys * 16 + (q4 & 1) * 8) = st;
    }
    // stage W (fp32 -> fp16, swizzled)
    #pragma unroll
    for (int i = 0; i < 32; i++) {
        int f = i * 128 + t;              // 0..4095
        int row = f >> 5, q4 = f & 31;
        float4 v = *(const float4*)&W[(long)row * F1 + q4 * 4];
        __half2 p0 = __floats2half2_rn(v.x, v.y);
        __half2 p1 = __floats2half2_rn(v.z, v.w);
        uint2 st;
        st.x = *(unsigned*)&p0;
        st.y = *(unsigned*)&p1;
        int phys = (q4 >> 1) ^ (row & 7);
        *(uint2*)((char*)Ws + row * 256 + phys * 16 + (q4 & 1) * 8) = st;
    }
    __syncthreads();

    float acc[16][4] = {};
    const int arow = w * 16 + (lane & 15);
    const int brow_lane = lane & 15;

    #pragma unroll
    for (int s = 0; s < 8; s++) {
        unsigned a0, a1, a2, a3;
        int ag = (s * 2 + (lane >> 4)) ^ (arow & 7);
        ldm_a4(a0, a1, a2, a3, smaddr((char*)Xs + arow * 256 + ag * 16));
        int brow = s * 16 + brow_lane;
        #pragma unroll
        for (int j = 0; j < 16; j++) {
            unsigned b0, b1;
            int bg = j ^ (brow & 7);
            ldm_b2t(b0, b1, smaddr((char*)Ws + brow * 256 + bg * 16));
            mma16816(acc[j], a0, a1, a2, a3, b0, b1);
        }
    }

    // epilogue: fp16 h store + per-head logits
    const int r0 = lane >> 2, q = lane & 3;
    const int n_a = base + w * 16 + r0;
    const int n_b = n_a + 8;
    float as0[4] = {}, ad0[4] = {}, as1[4] = {}, ad1[4] = {};
    #pragma unroll
    for (int j = 0; j < 16; j++) {
        int col = 8 * j + 2 * q;
        int hd = j >> 2;
        float aSx = attS[col], aSy = attS[col + 1];
        float aDx = attD[col], aDy = attD[col + 1];
        as0[hd] += acc[j][0] * aSx + acc[j][1] * aSy;
        ad0[hd] += acc[j][0] * aDx + acc[j][1] * aDy;
        as1[hd] += acc[j][2] * aSx + acc[j][3] * aSy;
        ad1[hd] += acc[j][2] * aDx + acc[j][3] * aDy;
        if (n_a < N_NODES) {
            __half2 h = __floats2half2_rn(acc[j][0], acc[j][1]);
            *(__half2*)&g_h1h[(long)n_a * F1 + col] = h;
        }
        if (n_b < N_NODES) {
            __half2 h = __floats2half2_rn(acc[j][2], acc[j][3]);
            *(__half2*)&g_h1h[(long)n_b * F1 + col] = h;
        }
    }
    #pragma unroll
    for (int hd = 0; hd < 4; hd++) {
        as0[hd] += __shfl_xor_sync(0xffffffffu, as0[hd], 1);
        as0[hd] += __shfl_xor_sync(0xffffffffu, as0[hd], 2);
        ad0[hd] += __shfl_xor_sync(0xffffffffu, ad0[hd], 1);
        ad0[hd] += __shfl_xor_sync(0xffffffffu, ad0[hd], 2);
        as1[hd] += __shfl_xor_sync(0xffffffffu, as1[hd], 1);
        as1[hd] += __shfl_xor_sync(0xffffffffu, as1[hd], 2);
        ad1[hd] += __shfl_xor_sync(0xffffffffu, ad1[hd], 1);
        ad1[hd] += __shfl_xor_sync(0xffffffffu, ad1[hd], 2);
    }
    if (q == 0) {
        if (n_a < N_NODES) {
            *(float4*)&g_as1[n_a * H1] = make_float4(as0[0], as0[1], as0[2], as0[3]);
            *(float4*)&g_ad1[n_a * H1] = make_float4(ad0[0], ad0[1], ad0[2], ad0[3]);
        }
        if (n_b < N_NODES) {
            *(float4*)&g_as1[n_b * H1] = make_float4(as1[0], as1[1], as1[2], as1[3]);
            *(float4*)&g_ad1[n_b * H1] = make_float4(ad1[0], ad1[1], ad1[2], ad1[3]);
        }
    }
}

// ---------------- layer1 fused aggregate (warp/node, fp16 gather) ----------------
__global__ __launch_bounds__(256) void agg1_kernel() {
    int warp = (blockIdx.x * 256 + threadIdx.x) >> 5;
    int lane = threadIdx.x & 31;
    if (warp >= N_NODES) return;
    const int n = warp;
    const int beg = g_off[n], end = g_off[n + 1];
    const int h = lane >> 3;

    const float adh = g_ad1[n * H1 + h];
    float4 acc = make_float4(0.f, 0.f, 0.f, 0.f);
    float z = 0.f;
    for (int p = beg; p < end; p++) {
        int s = g_csr_src[p];
        float a = g_as1[s * H1 + h];
        uint2 v = *(const uint2*)&g_h1h[(long)s * F1 + lane * 4];
        float e = __expf(lrelu(a + adh));
        z += e;
        float2 f01 = __half22float2(*(__half2*)&v.x);
        float2 f23 = __half22float2(*(__half2*)&v.y);
        acc.x = fmaf(e, f01.x, acc.x);
        acc.y = fmaf(e, f01.y, acc.y);
        acc.z = fmaf(e, f23.x, acc.z);
        acc.w = fmaf(e, f23.y, acc.w);
    }
    float inv = 1.f / (z + EPS_Z);
    float4 o;
    o.x = acc.x * inv; o.y = acc.y * inv; o.z = acc.z * inv; o.w = acc.w * inv;
    *(float4*)&g_agg1[(long)n * F1 + lane * 4] = o;
}

// ---------------- layer2 GEMM: 16 nodes/block, 2 nodes/thread ----------------
__global__ __launch_bounds__(128) void gemm2_kernel(
    const float* __restrict__ b1, const float* __restrict__ W,
    const float* __restrict__ attS, const float* __restrict__ attD)
{
    __shared__ float2 xs2[16][F1];
    const int t = threadIdx.x;
    const int quad = t & 15, slot = t >> 4;
    const int base = blockIdx.x * 16;

    #pragma unroll
    for (int r = 0; r < 16; r++) {
        float v = fmaxf(g_agg1[(long)(base + r) * F1 + t] + b1[t], 0.f);
        xs2[r][t] = make_float2(v, v);
    }
    __syncthreads();

    const int r0 = slot * 2, r1 = slot * 2 + 1;
    ull a00 = 0, a01 = 0, a10 = 0, a11 = 0;
    const float* Wp = W + quad * 4;
    #pragma unroll 4
    for (int k = 0; k < F1; k++) {
        ulonglong2 w = *(const ulonglong2*)(Wp + (long)k * F2);
        ull xa = *(const ull*)&xs2[r0][k];
        ull xb = *(const ull*)&xs2[r1][k];
        ffma2(a00, w.x, xa); ffma2(a01, w.y, xa);
        ffma2(a10, w.x, xb); ffma2(a11, w.y, xb);
    }

    float4 aS = *(const float4*)&attS[quad * 4];
    float4 aD = *(const float4*)&attD[quad * 4];

    ull pa[2] = {a00, a10}, pb[2] = {a01, a11};
    #pragma unroll
    for (int r = 0; r < 2; r++) {
        int n = base + slot * 2 + r;
        float v0, v1, v2, v3;
        unpack2(pa[r], v0, v1);
        unpack2(pb[r], v2, v3);
        __half2 h01 = __floats2half2_rn(v0, v1);
        __half2 h23 = __floats2half2_rn(v2, v3);
        uint2 pk;
        pk.x = *(unsigned*)&h01;
        pk.y = *(unsigned*)&h23;
        *(uint2*)&g_h2h[(long)n * F2 + quad * 4] = pk;
        float ps = v0 * aS.x + v1 * aS.y + v2 * aS.z + v3 * aS.w;
        float pd = v0 * aD.x + v1 * aD.y + v2 * aD.z + v3 * aD.w;
        #pragma unroll
        for (int off = 8; off > 0; off >>= 1) {
            ps += __shfl_down_sync(0xffffffffu, ps, off, 16);
            pd += __shfl_down_sync(0xffffffffu, pd, off, 16);
        }
        if (quad == 0) {
            g_as2[n] = ps;
            g_ad2[n] = pd;
        }
    }
}

// ---------------- layer2 fused aggregate + bias + relu ----------------
__global__ __launch_bounds__(256) void agg2_kernel(float* __restrict__ out,
                                                   const float* __restrict__ b2) {
    int warp = (blockIdx.x * 256 + threadIdx.x) >> 5;
    int lane = threadIdx.x & 31;
    if (warp >= N_NODES) return;
    const int n = warp;
    const int beg = g_off[n], end = g_off[n + 1];

    const float ad = g_ad2[n];
    float2 acc = make_float2(0.f, 0.f);
    float z = 0.f;
    for (int p = beg; p < end; p++) {
        int s = g_csr_src[p];
        float a = g_as2[s];
        unsigned w = *(const unsigned*)&g_h2h[(long)s * F2 + lane * 2];
        float e = __expf(lrelu(a + ad));
        z += e;
        float2 f = __half22float2(*(__half2*)&w);
        acc.x = fmaf(e, f.x, acc.x);
        acc.y = fmaf(e, f.y, acc.y);
    }
    float inv = 1.f / (z + EPS_Z);
    float2 bb = *(const float2*)&b2[lane * 2];
    float2 o;
    o.x = fmaxf(acc.x * inv + bb.x, 0.f);
    o.y = fmaxf(acc.y * inv + bb.y, 0.f);
    *(float2*)&out[(long)n * F2 + lane * 2] = o;
}

// ---------------- host ----------------
extern "C" void kernel_launch(void* const* d_in, const int* in_sizes, int n_in,
                              void* d_out, int out_size)
{
    const float* x     = (const float*)d_in[0];
    const int*   ei    = (const int*)  d_in[1];
    const float* W1    = (const float*)d_in[2];
    const float* attS1 = (const float*)d_in[3];
    const float* attD1 = (const float*)d_in[4];
    const float* b1    = (const float*)d_in[5];
    const float* W2    = (const float*)d_in[6];
    const float* attS2 = (const float*)d_in[7];
    const float* attD2 = (const float*)d_in[8];
    const float* b2    = (const float*)d_in[9];
    float* out = (float*)d_out;

    static cudaStream_t s2 = nullptr;
    static cudaEvent_t evFork = nullptr, evJoin = nullptr;
    if (!s2) {
        cudaStreamCreateWithFlags(&s2, cudaStreamNonBlocking);
        cudaEventCreateWithFlags(&evFork, cudaEventDisableTiming);
        cudaEventCreateWithFlags(&evJoin, cudaEventDisableTiming);
    }

    const int TB = 256;

    cudaEventRecord(evFork, 0);
    cudaStreamWaitEvent(s2, evFork, 0);

    // launches 0..2: CSR front (main stream)
    zero_cnt_kernel<<<(N_NODES + TB - 1) / TB, TB>>>();
    hist_kernel<<<(N_EDGES + TB - 1) / TB, TB>>>(ei);
    scan1_kernel<<<SCAN_G, SCAN_B>>>();

    // launch 3: gemm1 on s2 (ncu profiles launch idx 3) overlapping CSR build
    gemm1_kernel<<<G1_GRID, 128, 0, s2>>>(x, W1, attS1, attD1);
    cudaEventRecord(evJoin, s2);

    // remaining CSR (main stream)
    scan2_kernel<<<1, 64>>>();
    scan3_kernel<<<SCAN_G, SCAN_B>>>();
    scatter_kernel<<<(N_EDGES + TB - 1) / TB, TB>>>(ei);

    // join, then layer-1 aggregate + layer 2 (main stream)
    cudaStreamWaitEvent(0, evJoin, 0);
    agg1_kernel<<<(N_NODES * 32 + TB - 1) / TB, TB>>>();
    gemm2_kernel<<<N_NODES / 16, 128>>>(b1, W2, attS2, attD2);
    agg2_kernel<<<(N_NODES * 32 + TB - 1) / TB, TB>>>(out, b2);
}

// round 13
// speedup vs baseline: 2.1226x; 1.3954x over previous
#include <cuda_runtime.h>
#include <cuda_fp16.h>

#define N_NODES 50000
#define N_EDGES 800000
#define E_TOT   850000
#define F0      128
#define F1      128
#define H1      4
#define C1      32
#define F2      64
#define NEG     0.2f
#define EPS_Z   1e-16f

#define SCAN_B  1024
#define SCAN_G  ((N_NODES + SCAN_B - 1) / SCAN_B)   // 49
#define G1_BM   64
#define G1_GRID ((N_NODES + G1_BM - 1) / G1_BM)     // 782

typedef unsigned long long ull;

// ---------------- scratch ----------------
__device__ __half g_h1h[N_NODES * F1];
__device__ float  g_as1[N_NODES * H1];
__device__ float  g_ad1[N_NODES * H1];
__device__ __half g_agg1h[N_NODES * F1];   // relu(agg+b1), fp16 (layer-2 input)
__device__ __half g_h2h[N_NODES * F2];
__device__ float  g_as2[N_NODES];
__device__ float  g_ad2[N_NODES];
__device__ int    g_deg[N_NODES];
__device__ int    g_cur[N_NODES];
__device__ int    g_off[N_NODES + 1];
__device__ int    g_bsum[SCAN_G];
__device__ int    g_csr_src[E_TOT];

__device__ __forceinline__ float lrelu(float a) { return (a > 0.f) ? a : NEG * a; }

__device__ __forceinline__ unsigned smaddr(const void* p) {
    return (unsigned)__cvta_generic_to_shared(p);
}
__device__ __forceinline__ void ldm_a4(unsigned& a0, unsigned& a1, unsigned& a2, unsigned& a3,
                                       unsigned addr) {
    asm volatile("ldmatrix.sync.aligned.m8n8.x4.shared.b16 {%0,%1,%2,%3}, [%4];"
                 : "=r"(a0), "=r"(a1), "=r"(a2), "=r"(a3) : "r"(addr));
}
__device__ __forceinline__ void ldm_b2t(unsigned& b0, unsigned& b1, unsigned addr) {
    asm volatile("ldmatrix.sync.aligned.m8n8.x2.trans.shared.b16 {%0,%1}, [%2];"
                 : "=r"(b0), "=r"(b1) : "r"(addr));
}
__device__ __forceinline__ void mma16816(float* d,
                                         unsigned a0, unsigned a1, unsigned a2, unsigned a3,
                                         unsigned b0, unsigned b1) {
    asm volatile("mma.sync.aligned.m16n8k16.row.col.f32.f16.f16.f32 "
                 "{%0,%1,%2,%3}, {%4,%5,%6,%7}, {%8,%9}, {%0,%1,%2,%3};"
                 : "+f"(d[0]), "+f"(d[1]), "+f"(d[2]), "+f"(d[3])
                 : "r"(a0), "r"(a1), "r"(a2), "r"(a3), "r"(b0), "r"(b1));
}

// ---------------- CSR build ----------------
__global__ void zero_cnt_kernel() {
    int i = blockIdx.x * blockDim.x + threadIdx.x;
    if (i < N_NODES) g_deg[i] = 1;        // self loop pre-counted
}

__global__ void hist_kernel(const int* __restrict__ ei) {
    int e = blockIdx.x * blockDim.x + threadIdx.x;
    if (e >= N_EDGES) return;
    atomicAdd(&g_deg[ei[N_EDGES + e]], 1);
}

__global__ __launch_bounds__(SCAN_B) void scan1_kernel() {
    const int t = threadIdx.x, b = blockIdx.x;
    const int lane = t & 31, warp = t >> 5;
    int i = b * SCAN_B + t;
    int v = (i < N_NODES) ? g_deg[i] : 0;
    int s = v;
    #pragma unroll
    for (int off = 1; off < 32; off <<= 1) {
        int u = __shfl_up_sync(0xffffffffu, s, off);
        if (lane >= off) s += u;
    }
    __shared__ int wsum[32];
    if (lane == 31) wsum[warp] = s;
    __syncthreads();
    if (warp == 0) {
        int ws = wsum[lane];
        #pragma unroll
        for (int off = 1; off < 32; off <<= 1) {
            int u = __shfl_up_sync(0xffffffffu, ws, off);
            if (lane >= off) ws += u;
        }
        wsum[lane] = ws;
    }
    __syncthreads();
    int add = (warp > 0) ? wsum[warp - 1] : 0;
    s += add;
    if (i < N_NODES) g_off[i] = s - v;    // chunk-local exclusive
    if (t == SCAN_B - 1) g_bsum[b] = s;
}

// fused scan2+scan3: per-block prefix over bsum + global offsets + CSR seed
__global__ __launch_bounds__(SCAN_B) void scan23_kernel() {
    const int t = threadIdx.x, b = blockIdx.x;
    __shared__ int spre;
    if (t == 0) spre = 0;
    __syncthreads();
    if (t < b) atomicAdd(&spre, g_bsum[t]);   // b <= 48 loads
    __syncthreads();
    int prefix = spre;
    int i = b * SCAN_B + t;
    if (i < N_NODES) {
        int o = g_off[i] + prefix;
        g_off[i] = o;
        g_csr_src[o] = i;     // self loop in first slot
        g_cur[i] = o + 1;
    }
    if (b == SCAN_G - 1 && t == 0)
        g_off[N_NODES] = prefix + g_bsum[SCAN_G - 1];
}

__global__ void scatter_kernel(const int* __restrict__ ei) {
    int e = blockIdx.x * blockDim.x + threadIdx.x;
    if (e >= N_EDGES) return;
    int s = ei[e];
    int d = ei[N_EDGES + e];
    int pos = atomicAdd(&g_cur[d], 1);
    g_csr_src[pos] = s;
}

// ---------------- layer1 GEMM via fp16 tensor cores ----------------
__global__ __launch_bounds__(128) void gemm1_kernel(
    const float* __restrict__ x, const float* __restrict__ W,
    const float* __restrict__ attS, const float* __restrict__ attD)
{
    __shared__ __align__(16) __half Xs[G1_BM * F0];
    __shared__ __align__(16) __half Ws[F0 * F1];
    const int t = threadIdx.x;
    const int lane = t & 31, w = t >> 5;
    const int base = blockIdx.x * G1_BM;

    #pragma unroll
    for (int i = 0; i < 16; i++) {
        int f = i * 128 + t;
        int row = f >> 5, q4 = f & 31;
        int n = base + row;
        float4 v = (n < N_NODES) ? *(const float4*)&x[(long)n * F0 + q4 * 4]
                                 : make_float4(0.f, 0.f, 0.f, 0.f);
        __half2 p0 = __floats2half2_rn(v.x, v.y);
        __half2 p1 = __floats2half2_rn(v.z, v.w);
        uint2 st;
        st.x = *(unsigned*)&p0;
        st.y = *(unsigned*)&p1;
        int phys = (q4 >> 1) ^ (row & 7);
        *(uint2*)((char*)Xs + row * 256 + phys * 16 + (q4 & 1) * 8) = st;
    }
    #pragma unroll
    for (int i = 0; i < 32; i++) {
        int f = i * 128 + t;
        int row = f >> 5, q4 = f & 31;
        float4 v = *(const float4*)&W[(long)row * F1 + q4 * 4];
        __half2 p0 = __floats2half2_rn(v.x, v.y);
        __half2 p1 = __floats2half2_rn(v.z, v.w);
        uint2 st;
        st.x = *(unsigned*)&p0;
        st.y = *(unsigned*)&p1;
        int phys = (q4 >> 1) ^ (row & 7);
        *(uint2*)((char*)Ws + row * 256 + phys * 16 + (q4 & 1) * 8) = st;
    }
    __syncthreads();

    float acc[16][4] = {};
    const int arow = w * 16 + (lane & 15);
    const int brow_lane = lane & 15;

    #pragma unroll
    for (int s = 0; s < 8; s++) {
        unsigned a0, a1, a2, a3;
        int ag = (s * 2 + (lane >> 4)) ^ (arow & 7);
        ldm_a4(a0, a1, a2, a3, smaddr((char*)Xs + arow * 256 + ag * 16));
        int brow = s * 16 + brow_lane;
        #pragma unroll
        for (int j = 0; j < 16; j++) {
            unsigned b0, b1;
            int bg = j ^ (brow & 7);
            ldm_b2t(b0, b1, smaddr((char*)Ws + brow * 256 + bg * 16));
            mma16816(acc[j], a0, a1, a2, a3, b0, b1);
        }
    }

    const int r0 = lane >> 2, q = lane & 3;
    const int n_a = base + w * 16 + r0;
    const int n_b = n_a + 8;
    float as0[4] = {}, ad0[4] = {}, as1[4] = {}, ad1[4] = {};
    #pragma unroll
    for (int j = 0; j < 16; j++) {
        int col = 8 * j + 2 * q;
        int hd = j >> 2;
        float aSx = attS[col], aSy = attS[col + 1];
        float aDx = attD[col], aDy = attD[col + 1];
        as0[hd] += acc[j][0] * aSx + acc[j][1] * aSy;
        ad0[hd] += acc[j][0] * aDx + acc[j][1] * aDy;
        as1[hd] += acc[j][2] * aSx + acc[j][3] * aSy;
        ad1[hd] += acc[j][2] * aDx + acc[j][3] * aDy;
        if (n_a < N_NODES) {
            __half2 h = __floats2half2_rn(acc[j][0], acc[j][1]);
            *(__half2*)&g_h1h[(long)n_a * F1 + col] = h;
        }
        if (n_b < N_NODES) {
            __half2 h = __floats2half2_rn(acc[j][2], acc[j][3]);
            *(__half2*)&g_h1h[(long)n_b * F1 + col] = h;
        }
    }
    #pragma unroll
    for (int hd = 0; hd < 4; hd++) {
        as0[hd] += __shfl_xor_sync(0xffffffffu, as0[hd], 1);
        as0[hd] += __shfl_xor_sync(0xffffffffu, as0[hd], 2);
        ad0[hd] += __shfl_xor_sync(0xffffffffu, ad0[hd], 1);
        ad0[hd] += __shfl_xor_sync(0xffffffffu, ad0[hd], 2);
        as1[hd] += __shfl_xor_sync(0xffffffffu, as1[hd], 1);
        as1[hd] += __shfl_xor_sync(0xffffffffu, as1[hd], 2);
        ad1[hd] += __shfl_xor_sync(0xffffffffu, ad1[hd], 1);
        ad1[hd] += __shfl_xor_sync(0xffffffffu, ad1[hd], 2);
    }
    if (q == 0) {
        if (n_a < N_NODES) {
            *(float4*)&g_as1[n_a * H1] = make_float4(as0[0], as0[1], as0[2], as0[3]);
            *(float4*)&g_ad1[n_a * H1] = make_float4(ad0[0], ad0[1], ad0[2], ad0[3]);
        }
        if (n_b < N_NODES) {
            *(float4*)&g_as1[n_b * H1] = make_float4(as1[0], as1[1], as1[2], as1[3]);
            *(float4*)&g_ad1[n_b * H1] = make_float4(ad1[0], ad1[1], ad1[2], ad1[3]);
        }
    }
}

// ---------------- layer1 aggregate + bias + relu, fp16 out ----------------
__global__ __launch_bounds__(256) void agg1_kernel(const float* __restrict__ b1) {
    int warp = (blockIdx.x * 256 + threadIdx.x) >> 5;
    int lane = threadIdx.x & 31;
    if (warp >= N_NODES) return;
    const int n = warp;
    const int beg = g_off[n], end = g_off[n + 1];
    const int h = lane >> 3;

    const float adh = g_ad1[n * H1 + h];
    float4 acc = make_float4(0.f, 0.f, 0.f, 0.f);
    float z = 0.f;
    for (int p = beg; p < end; p++) {
        int s = g_csr_src[p];
        float a = g_as1[s * H1 + h];
        uint2 v = *(const uint2*)&g_h1h[(long)s * F1 + lane * 4];
        float e = __expf(lrelu(a + adh));
        z += e;
        float2 f01 = __half22float2(*(__half2*)&v.x);
        float2 f23 = __half22float2(*(__half2*)&v.y);
        acc.x = fmaf(e, f01.x, acc.x);
        acc.y = fmaf(e, f01.y, acc.y);
        acc.z = fmaf(e, f23.x, acc.z);
        acc.w = fmaf(e, f23.y, acc.w);
    }
    float inv = 1.f / (z + EPS_Z);
    float4 bb = *(const float4*)&b1[lane * 4];
    float o0 = fmaxf(acc.x * inv + bb.x, 0.f);
    float o1 = fmaxf(acc.y * inv + bb.y, 0.f);
    float o2 = fmaxf(acc.z * inv + bb.z, 0.f);
    float o3 = fmaxf(acc.w * inv + bb.w, 0.f);
    __half2 p0 = __floats2half2_rn(o0, o1);
    __half2 p1 = __floats2half2_rn(o2, o3);
    uint2 pk;
    pk.x = *(unsigned*)&p0;
    pk.y = *(unsigned*)&p1;
    *(uint2*)&g_agg1h[(long)n * F1 + lane * 4] = pk;
}

// ---------------- layer2 GEMM via fp16 tensor cores (BN=64) ----------------
__global__ __launch_bounds__(128) void gemm2_kernel(
    const float* __restrict__ W,
    const float* __restrict__ attS, const float* __restrict__ attD)
{
    __shared__ __align__(16) __half Xs[G1_BM * F1];   // 64x128
    __shared__ __align__(16) __half Ws[F1 * F2];      // 128x64
    const int t = threadIdx.x;
    const int lane = t & 31, w = t >> 5;
    const int base = blockIdx.x * G1_BM;

    // stage X tile from fp16 agg1 (copy, swizzled)
    #pragma unroll
    for (int i = 0; i < 16; i++) {
        int f = i * 128 + t;
        int row = f >> 5, q4 = f & 31;
        int n = base + row;
        uint2 st = make_uint2(0u, 0u);
        if (n < N_NODES) st = *(const uint2*)&g_agg1h[(long)n * F1 + q4 * 4];
        int phys = (q4 >> 1) ^ (row & 7);
        *(uint2*)((char*)Xs + row * 256 + phys * 16 + (q4 & 1) * 8) = st;
    }
    // stage W2 (fp32 -> fp16, swizzled; 64 cols = 128B/row, 8 granules)
    #pragma unroll
    for (int i = 0; i < 16; i++) {
        int f = i * 128 + t;              // 0..2047
        int row = f >> 4, q4 = f & 15;    // 128 rows x 16 float4
        float4 v = *(const float4*)&W[(long)row * F2 + q4 * 4];
        __half2 p0 = __floats2half2_rn(v.x, v.y);
        __half2 p1 = __floats2half2_rn(v.z, v.w);
        uint2 st;
        st.x = *(unsigned*)&p0;
        st.y = *(unsigned*)&p1;
        int phys = (q4 >> 1) ^ (row & 7);
        *(uint2*)((char*)Ws + row * 128 + phys * 16 + (q4 & 1) * 8) = st;
    }
    __syncthreads();

    float acc[8][4] = {};
    const int arow = w * 16 + (lane & 15);
    const int brow_lane = lane & 15;

    #pragma unroll
    for (int s = 0; s < 8; s++) {
        unsigned a0, a1, a2, a3;
        int ag = (s * 2 + (lane >> 4)) ^ (arow & 7);
        ldm_a4(a0, a1, a2, a3, smaddr((char*)Xs + arow * 256 + ag * 16));
        int brow = s * 16 + brow_lane;
        #pragma unroll
        for (int j = 0; j < 8; j++) {
            unsigned b0, b1;
            int bg = j ^ (brow & 7);
            ldm_b2t(b0, b1, smaddr((char*)Ws + brow * 128 + bg * 16));
            mma16816(acc[j], a0, a1, a2, a3, b0, b1);
        }
    }

    const int r0 = lane >> 2, q = lane & 3;
    const int n_a = base + w * 16 + r0;
    const int n_b = n_a + 8;
    float as0 = 0.f, ad0 = 0.f, as1 = 0.f, ad1 = 0.f;
    #pragma unroll
    for (int j = 0; j < 8; j++) {
        int col = 8 * j + 2 * q;
        float aSx = attS[col], aSy = attS[col + 1];
        float aDx = attD[col], aDy = attD[col + 1];
        as0 += acc[j][0] * aSx + acc[j][1] * aSy;
        ad0 += acc[j][0] * aDx + acc[j][1] * aDy;
        as1 += acc[j][2] * aSx + acc[j][3] * aSy;
        ad1 += acc[j][2] * aDx + acc[j][3] * aDy;
        if (n_a < N_NODES) {
            __half2 h = __floats2half2_rn(acc[j][0], acc[j][1]);
            *(__half2*)&g_h2h[(long)n_a * F2 + col] = h;
        }
        if (n_b < N_NODES) {
            __half2 h = __floats2half2_rn(acc[j][2], acc[j][3]);
            *(__half2*)&g_h2h[(long)n_b * F2 + col] = h;
        }
    }
    as0 += __shfl_xor_sync(0xffffffffu, as0, 1);
    as0 += __shfl_xor_sync(0xffffffffu, as0, 2);
    ad0 += __shfl_xor_sync(0xffffffffu, ad0, 1);
    ad0 += __shfl_xor_sync(0xffffffffu, ad0, 2);
    as1 += __shfl_xor_sync(0xffffffffu, as1, 1);
    as1 += __shfl_xor_sync(0xffffffffu, as1, 2);
    ad1 += __shfl_xor_sync(0xffffffffu, ad1, 1);
    ad1 += __shfl_xor_sync(0xffffffffu, ad1, 2);
    if (q == 0) {
        if (n_a < N_NODES) { g_as2[n_a] = as0; g_ad2[n_a] = ad0; }
        if (n_b < N_NODES) { g_as2[n_b] = as1; g_ad2[n_b] = ad1; }
    }
}

// ---------------- layer2 fused aggregate + bias + relu ----------------
__global__ __launch_bounds__(256) void agg2_kernel(float* __restrict__ out,
                                                   const float* __restrict__ b2) {
    int warp = (blockIdx.x * 256 + threadIdx.x) >> 5;
    int lane = threadIdx.x & 31;
    if (warp >= N_NODES) return;
    const int n = warp;
    const int beg = g_off[n], end = g_off[n + 1];

    const float ad = g_ad2[n];
    float2 acc = make_float2(0.f, 0.f);
    float z = 0.f;
    for (int p = beg; p < end; p++) {
        int s = g_csr_src[p];
        float a = g_as2[s];
        unsigned w = *(const unsigned*)&g_h2h[(long)s * F2 + lane * 2];
        float e = __expf(lrelu(a + ad));
        z += e;
        float2 f = __half22float2(*(__half2*)&w);
        acc.x = fmaf(e, f.x, acc.x);
        acc.y = fmaf(e, f.y, acc.y);
    }
    float inv = 1.f / (z + EPS_Z);
    float2 bb = *(const float2*)&b2[lane * 2];
    float2 o;
    o.x = fmaxf(acc.x * inv + bb.x, 0.f);
    o.y = fmaxf(acc.y * inv + bb.y, 0.f);
    *(float2*)&out[(long)n * F2 + lane * 2] = o;
}

// ---------------- host ----------------
extern "C" void kernel_launch(void* const* d_in, const int* in_sizes, int n_in,
                              void* d_out, int out_size)
{
    const float* x     = (const float*)d_in[0];
    const int*   ei    = (const int*)  d_in[1];
    const float* W1    = (const float*)d_in[2];
    const float* attS1 = (const float*)d_in[3];
    const float* attD1 = (const float*)d_in[4];
    const float* b1    = (const float*)d_in[5];
    const float* W2    = (const float*)d_in[6];
    const float* attS2 = (const float*)d_in[7];
    const float* attD2 = (const float*)d_in[8];
    const float* b2    = (const float*)d_in[9];
    float* out = (float*)d_out;

    static cudaStream_t s2 = nullptr;
    static cudaEvent_t evFork = nullptr, evJoin = nullptr;
    if (!s2) {
        cudaStreamCreateWithFlags(&s2, cudaStreamNonBlocking);
        cudaEventCreateWithFlags(&evFork, cudaEventDisableTiming);
        cudaEventCreateWithFlags(&evJoin, cudaEventDisableTiming);
    }

    const int TB = 256;

    cudaEventRecord(evFork, 0);
    cudaStreamWaitEvent(s2, evFork, 0);

    // CSR front (main stream)
    zero_cnt_kernel<<<(N_NODES + TB - 1) / TB, TB>>>();
    hist_kernel<<<(N_EDGES + TB - 1) / TB, TB>>>(ei);
    scan1_kernel<<<SCAN_G, SCAN_B>>>();

    // launch 4: gemm1 on s2 (profiled) overlapping CSR build
    gemm1_kernel<<<G1_GRID, 128, 0, s2>>>(x, W1, attS1, attD1);
    cudaEventRecord(evJoin, s2);

    // remaining CSR (main stream)
    scan23_kernel<<<SCAN_G, SCAN_B>>>();
    scatter_kernel<<<(N_EDGES + TB - 1) / TB, TB>>>(ei);

    // join, then layer-1 aggregate + layer 2
    cudaStreamWaitEvent(0, evJoin, 0);
    agg1_kernel<<<(N_NODES * 32 + TB - 1) / TB, TB>>>(b1);
    gemm2_kernel<<<G1_GRID, 128>>>(W2, attS2, attD2);
    agg2_kernel<<<(N_NODES * 32 + TB - 1) / TB, TB>>>(out, b2);
}